// round 1
// baseline (speedup 1.0000x reference)
#include <cuda_runtime.h>

// ---------------------------------------------------------------------------
// WaveNet Mel2Raw  —  fp32 baseline, layer-sequenced register-tiled GEMMs
// B=2, T=L=32512, R=64, S=128, NM=80, NC=256, NB=30, KC=2, HOP=256, UK=512
// ---------------------------------------------------------------------------

namespace {

constexpr int Bn  = 2;
constexpr int Ln  = 32512;
constexpr int Rn  = 64;
constexpr int Sn  = 128;
constexpr int NMn = 80;
constexpr int NCn = 256;
constexpr int NBn = 30;

// Scratch (static device globals: allocation-free, graph-safe)
__device__ float g_cond[Bn * NMn * Ln];   // [b][80][L]
__device__ float g_res [Bn * Rn  * Ln];   // [b][64][L]
__device__ float g_skip[Bn * Sn  * Ln];   // [b][128][L]
__device__ float g_h   [Bn * Rn  * Ln];   // [b][64][L]
__device__ float g_y1  [Bn * NCn * Ln];   // [b][256][L]

__device__ __forceinline__ float ex2f(float x) {
    float y; asm("ex2.approx.f32 %0, %1;" : "=f"(y) : "f"(x)); return y;
}
__device__ __forceinline__ float rcpf(float x) {
    float y; asm("rcp.approx.f32 %0, %1;" : "=f"(y) : "f"(x)); return y;
}
// tanh(f) * sigmoid(g) via EX2/RCP (rel err ~1e-6, MUFU-only)
__device__ __forceinline__ float gate_fn(float f, float g) {
    float ef = ex2f(2.8853900817779268f * f);          // e^(2f)
    float th = 1.0f - 2.0f * rcpf(ef + 1.0f);          // tanh(f)
    float sg = rcpf(1.0f + ex2f(-1.4426950408889634f * g)); // sigmoid(g)
    return th * sg;
}

__device__ __forceinline__ void ld4(float* d, const float* s) {
    float4 v = *(const float4*)s;
    d[0] = v.x; d[1] = v.y; d[2] = v.z; d[3] = v.w;
}
__device__ __forceinline__ void st4(float* d, const float* s) {
    float4 v; v.x = s[0]; v.y = s[1]; v.z = s[2]; v.w = s[3];
    *(float4*)d = v;
}

// ---------------------------------------------------------------------------
// cond: transposed conv (lhs_dilation=256, K=512, pad 255) -> exactly 2 taps
// cond[b,c,t] = mel_b[c] + sum_ci w[c,ci,255-r]*mel[b,ci,q] + w[c,ci,511-r]*mel[b,ci,q+1]
//   q = t>>8, r = t&255   (both taps always in-bounds: q <= 126)
// ---------------------------------------------------------------------------
__global__ __launch_bounds__(256) void cond_kernel(
    const float* __restrict__ mels, const float* __restrict__ mel_w,
    const float* __restrict__ mel_b)
{
    __shared__ float m0[NMn], m1[NMn];
    const int b  = blockIdx.y;
    const int t0 = blockIdx.x * 128;          // tile lies within one 256-block
    const int q  = t0 >> 8;
    const int tid = threadIdx.x;
    if (tid < NMn) {
        m0[tid] = mels[(b * NMn + tid) * 128 + q];
        m1[tid] = mels[(b * NMn + tid) * 128 + q + 1];
    }
    __syncthreads();
    for (int j = tid; j < NMn * 128; j += 256) {
        const int c  = j >> 7;
        const int tt = j & 127;
        const int t  = t0 + tt;
        const int r  = t & 255;
        const float* w = mel_w + c * (NMn * 512);
        float acc = mel_b[c];
        #pragma unroll 4
        for (int ci = 0; ci < NMn; ci++) {
            acc += w[ci * 512 + 255 - r] * m0[ci];
            acc += w[ci * 512 + 511 - r] * m1[ci];
        }
        g_cond[(b * NMn + c) * Ln + t] = acc;
    }
}

// ---------------------------------------------------------------------------
// init: res = input_w[r]*x + input_b[r];  skip = 0
// ---------------------------------------------------------------------------
__global__ void init_kernel(const float* __restrict__ x,
                            const float* __restrict__ iw,
                            const float* __restrict__ ib)
{
    const int stride = gridDim.x * blockDim.x;
    const int tid0   = blockIdx.x * blockDim.x + threadIdx.x;
    for (int i = tid0; i < Bn * Rn * Ln; i += stride) {
        const int t = i % Ln;
        const int r = (i / Ln) % Rn;
        const int b = i / (Ln * Rn);
        g_res[i] = iw[r] * x[b * Ln + t] + ib[r];
    }
    for (int i = tid0; i < Bn * Sn * Ln; i += stride) g_skip[i] = 0.0f;
}

// ---------------------------------------------------------------------------
// Z kernel: z = Wd(tap0)*res[t-d] + Wd(tap1)*res[t] + Wc*cond + (bd+bc)
//           h = tanh(z_f) * sigmoid(z_g)   -> g_h
// CTA: one (b, 128-t tile). 256 threads, thread tile = (4 f-rows + 4 g-rows) x 8 t
// ---------------------------------------------------------------------------
constexpr int ZROW  = 132;                       // padded row (bank-conflict-free)
constexpr int Z_WD  = 2 * 64 * ZROW;             // 16896
constexpr int Z_WC  = NMn * ZROW;                // 10560
constexpr int Z_ACT = 64 * ZROW;                 // 8448
constexpr int Z_SMF = Z_WD + Z_WC + 2 * Z_ACT + NMn * ZROW;   // 54912 floats

__global__ __launch_bounds__(256) void z_kernel(
    const float* __restrict__ dil_w,  const float* __restrict__ dil_b,
    const float* __restrict__ cond_w, const float* __restrict__ cond_b,
    int blk)
{
    extern __shared__ float sm[];
    float* s_wd   = sm;                    // [2][64][132]  (tap, ci, co)
    float* s_wc   = sm + Z_WD;             // [80][132]     (ci, co)
    float* s_prev = s_wc + Z_WC;           // [64][132]
    float* s_cur  = s_prev + Z_ACT;        // [64][132]
    float* s_cond = s_cur + Z_ACT;         // [80][132]

    const int d = 1 << (blk % 10);
    const float* wd = dil_w  + blk * (128 * 64 * 2);
    const float* wc = cond_w + blk * (128 * NMn);
    const float* bd = dil_b  + blk * 128;
    const float* bc = cond_b + blk * 128;

    const int b   = blockIdx.y;
    const int t0  = blockIdx.x * 128;
    const int tid = threadIdx.x;

    // stage dilated weights transposed: s_wd[tap][ci][co] = wd[co][ci][tap]
    for (int i = tid; i < 128 * 64 * 2; i += 256) {
        const int co = i >> 7, rem = i & 127, ci = rem >> 1, tap = rem & 1;
        s_wd[tap * (64 * ZROW) + ci * ZROW + co] = wd[i];
    }
    // stage cond weights transposed: s_wc[ci][co] = wc[co][ci]
    for (int i = tid; i < 128 * NMn; i += 256) {
        const int co = i / NMn, ci = i - co * NMn;
        s_wc[ci * ZROW + co] = wc[i];
    }
    // stage activations
    const float* resb = g_res + b * (Rn * Ln);
    for (int i = tid; i < 64 * 128; i += 256) {
        const int ci = i >> 7, tt = i & 127;
        s_cur[ci * ZROW + tt] = resb[ci * Ln + t0 + tt];
        const int tp = t0 - d + tt;
        s_prev[ci * ZROW + tt] = (tp >= 0) ? resb[ci * Ln + tp] : 0.0f;
    }
    const float* condb = g_cond + b * (NMn * Ln);
    for (int i = tid; i < NMn * 128; i += 256) {
        const int ci = i >> 7, tt = i & 127;
        s_cond[ci * ZROW + tt] = condb[ci * Ln + t0 + tt];
    }
    __syncthreads();

    const int tx = tid & 15, ty = tid >> 4;
    const int tb = tx * 8;          // 8 time steps
    const int cf = ty * 4;          // 4 f-rows (cf..cf+3) + 4 g-rows (cf+64..)

    float accF[4][8], accG[4][8];
    #pragma unroll
    for (int j = 0; j < 4; j++) {
        const float bf = bd[cf + j]      + bc[cf + j];
        const float bg = bd[cf + 64 + j] + bc[cf + 64 + j];
        #pragma unroll
        for (int t = 0; t < 8; t++) { accF[j][t] = bf; accG[j][t] = bg; }
    }

    // dilated conv: K = 64, 2 taps
    #pragma unroll 2
    for (int ci = 0; ci < 64; ci++) {
        float w0f[4], w0g[4], w1f[4], w1g[4], p[8], c[8];
        ld4(w0f, s_wd + ci * ZROW + cf);
        ld4(w0g, s_wd + ci * ZROW + cf + 64);
        ld4(w1f, s_wd + 64 * ZROW + ci * ZROW + cf);
        ld4(w1g, s_wd + 64 * ZROW + ci * ZROW + cf + 64);
        ld4(p,     s_prev + ci * ZROW + tb);
        ld4(p + 4, s_prev + ci * ZROW + tb + 4);
        ld4(c,     s_cur  + ci * ZROW + tb);
        ld4(c + 4, s_cur  + ci * ZROW + tb + 4);
        #pragma unroll
        for (int j = 0; j < 4; j++)
            #pragma unroll
            for (int t = 0; t < 8; t++) {
                accF[j][t] += w0f[j] * p[t];
                accF[j][t] += w1f[j] * c[t];
                accG[j][t] += w0g[j] * p[t];
                accG[j][t] += w1g[j] * c[t];
            }
    }
    // cond conv: K = 80
    #pragma unroll 2
    for (int ci = 0; ci < NMn; ci++) {
        float wf[4], wg[4], a[8];
        ld4(wf, s_wc + ci * ZROW + cf);
        ld4(wg, s_wc + ci * ZROW + cf + 64);
        ld4(a,     s_cond + ci * ZROW + tb);
        ld4(a + 4, s_cond + ci * ZROW + tb + 4);
        #pragma unroll
        for (int j = 0; j < 4; j++)
            #pragma unroll
            for (int t = 0; t < 8; t++) {
                accF[j][t] += wf[j] * a[t];
                accG[j][t] += wg[j] * a[t];
            }
    }

    // gate + write h (coalesced float4 stores)
    float* hb = g_h + b * (Rn * Ln) + t0 + tb;
    #pragma unroll
    for (int j = 0; j < 4; j++) {
        float o[8];
        #pragma unroll
        for (int t = 0; t < 8; t++) o[t] = gate_fn(accF[j][t], accG[j][t]);
        st4(hb + (cf + j) * Ln,     o);
        st4(hb + (cf + j) * Ln + 4, o + 4);
    }
}

// ---------------------------------------------------------------------------
// SR kernel: skip += Ws*h + bs ;  res += Wr*h + br
// Combined 192-row output; thread tile = 12 rows x 8 t
// ---------------------------------------------------------------------------
constexpr int SR_WROW = 196;
constexpr int SR_SMF  = 64 * SR_WROW + 64 * ZROW;   // 12544 + 8448 = 20992 floats

__global__ __launch_bounds__(256) void sr_kernel(
    const float* __restrict__ skip_w, const float* __restrict__ skip_b,
    const float* __restrict__ res_w,  const float* __restrict__ res_b,
    int blk)
{
    extern __shared__ float sm[];
    float* s_w = sm;                  // [64][196]: cols 0..127 = Ws, 128..191 = Wr
    float* s_h = sm + 64 * SR_WROW;   // [64][132]

    const float* ws = skip_w + blk * (128 * 64);
    const float* wr = res_w  + blk * (64 * 64);
    const float* bs = skip_b + blk * 128;
    const float* br = res_b  + blk * 64;

    const int b   = blockIdx.y;
    const int t0  = blockIdx.x * 128;
    const int tid = threadIdx.x;

    for (int i = tid; i < 128 * 64; i += 256) {
        const int co = i >> 6, ci = i & 63;
        s_w[ci * SR_WROW + co] = ws[i];
    }
    for (int i = tid; i < 64 * 64; i += 256) {
        const int co = i >> 6, ci = i & 63;
        s_w[ci * SR_WROW + 128 + co] = wr[i];
    }
    const float* hb = g_h + b * (Rn * Ln);
    for (int i = tid; i < 64 * 128; i += 256) {
        const int ci = i >> 7, tt = i & 127;
        s_h[ci * ZROW + tt] = hb[ci * Ln + t0 + tt];
    }
    __syncthreads();

    const int tx = tid & 15, ty = tid >> 4;
    const int tb = tx * 8, cb = ty * 12;

    float acc[12][8];
    #pragma unroll
    for (int j = 0; j < 12; j++) {
        const int row = cb + j;
        const float bias = (row < 128) ? bs[row] : br[row - 128];
        #pragma unroll
        for (int t = 0; t < 8; t++) acc[j][t] = bias;
    }

    #pragma unroll 2
    for (int ci = 0; ci < 64; ci++) {
        float w[12], h[8];
        ld4(w,     s_w + ci * SR_WROW + cb);
        ld4(w + 4, s_w + ci * SR_WROW + cb + 4);
        ld4(w + 8, s_w + ci * SR_WROW + cb + 8);
        ld4(h,     s_h + ci * ZROW + tb);
        ld4(h + 4, s_h + ci * ZROW + tb + 4);
        #pragma unroll
        for (int j = 0; j < 12; j++)
            #pragma unroll
            for (int t = 0; t < 8; t++) acc[j][t] += w[j] * h[t];
    }

    #pragma unroll
    for (int j = 0; j < 12; j++) {
        const int row = cb + j;
        float* dst = (row < 128)
            ? (g_skip + (b * Sn + row) * Ln + t0 + tb)
            : (g_res  + (b * Rn + (row - 128)) * Ln + t0 + tb);
        float4 o0 = *(float4*)dst;
        float4 o1 = *(float4*)(dst + 4);
        o0.x += acc[j][0]; o0.y += acc[j][1]; o0.z += acc[j][2]; o0.w += acc[j][3];
        o1.x += acc[j][4]; o1.y += acc[j][5]; o1.z += acc[j][6]; o1.w += acc[j][7];
        *(float4*)dst       = o0;
        *(float4*)(dst + 4) = o1;
    }
}

// ---------------------------------------------------------------------------
// post1: y1 = W1 * relu(skip) + b1     (256 x 128 GEMM, 64-t tiles)
// ---------------------------------------------------------------------------
constexpr int P1_WROW = 260;
constexpr int P1_SMF  = 128 * P1_WROW + 128 * 68;   // 33280 + 8704 = 41984 floats

__global__ __launch_bounds__(256) void p1_kernel(
    const float* __restrict__ w1, const float* __restrict__ b1)
{
    extern __shared__ float sm[];
    float* s_w = sm;                  // [128][260]
    float* s_a = sm + 128 * P1_WROW;  // [128][68]

    const int b   = blockIdx.y;
    const int t0  = blockIdx.x * 64;
    const int tid = threadIdx.x;

    for (int i = tid; i < 256 * 128; i += 256) {
        const int co = i >> 7, ci = i & 127;
        s_w[ci * P1_WROW + co] = w1[i];
    }
    const float* sk = g_skip + b * (Sn * Ln);
    for (int i = tid; i < 128 * 64; i += 256) {
        const int ci = i >> 6, tt = i & 63;
        s_a[ci * 68 + tt] = fmaxf(sk[ci * Ln + t0 + tt], 0.0f);
    }
    __syncthreads();

    const int tx = tid & 15, ty = tid >> 4;
    const int tb = tx * 4, cb = ty * 16;

    float acc[16][4];
    #pragma unroll
    for (int j = 0; j < 16; j++) {
        const float bias = b1[cb + j];
        #pragma unroll
        for (int t = 0; t < 4; t++) acc[j][t] = bias;
    }

    #pragma unroll 2
    for (int ci = 0; ci < 128; ci++) {
        float w[16], a[4];
        ld4(w,      s_w + ci * P1_WROW + cb);
        ld4(w + 4,  s_w + ci * P1_WROW + cb + 4);
        ld4(w + 8,  s_w + ci * P1_WROW + cb + 8);
        ld4(w + 12, s_w + ci * P1_WROW + cb + 12);
        ld4(a, s_a + ci * 68 + tb);
        #pragma unroll
        for (int j = 0; j < 16; j++)
            #pragma unroll
            for (int t = 0; t < 4; t++) acc[j][t] += w[j] * a[t];
    }

    #pragma unroll
    for (int j = 0; j < 16; j++)
        st4(g_y1 + (b * NCn + cb + j) * Ln + t0 + tb, acc[j]);
}

// ---------------------------------------------------------------------------
// post2: out = W2 * relu(y1) + b2     (128-co half per blockIdx.z, 64-t tiles)
// ---------------------------------------------------------------------------
constexpr int P2_SMF = 256 * ZROW + 256 * 68;   // 33792 + 17408 = 51200 floats

__global__ __launch_bounds__(256) void p2_kernel(
    const float* __restrict__ w2, const float* __restrict__ b2,
    float* __restrict__ out)
{
    extern __shared__ float sm[];
    float* s_w = sm;               // [256][132] (ci, co-local)
    float* s_a = sm + 256 * ZROW;  // [256][68]

    const int b    = blockIdx.y;
    const int t0   = blockIdx.x * 64;
    const int co0  = blockIdx.z * 128;
    const int tid  = threadIdx.x;

    for (int i = tid; i < 128 * 256; i += 256) {
        const int col = i >> 8, ci = i & 255;
        s_w[ci * ZROW + col] = w2[(co0 + col) * 256 + ci];
    }
    const float* y1b = g_y1 + b * (NCn * Ln);
    for (int i = tid; i < 256 * 64; i += 256) {
        const int ci = i >> 6, tt = i & 63;
        s_a[ci * 68 + tt] = fmaxf(y1b[ci * Ln + t0 + tt], 0.0f);
    }
    __syncthreads();

    const int tx = tid & 15, ty = tid >> 4;
    const int tb = tx * 4, cl = ty * 8;

    float acc[8][4];
    #pragma unroll
    for (int j = 0; j < 8; j++) {
        const float bias = b2[co0 + cl + j];
        #pragma unroll
        for (int t = 0; t < 4; t++) acc[j][t] = bias;
    }

    #pragma unroll 4
    for (int ci = 0; ci < 256; ci++) {
        float w[8], a[4];
        ld4(w,     s_w + ci * ZROW + cl);
        ld4(w + 4, s_w + ci * ZROW + cl + 4);
        ld4(a, s_a + ci * 68 + tb);
        #pragma unroll
        for (int j = 0; j < 8; j++)
            #pragma unroll
            for (int t = 0; t < 4; t++) acc[j][t] += w[j] * a[t];
    }

    #pragma unroll
    for (int j = 0; j < 8; j++)
        st4(out + (b * NCn + co0 + cl + j) * Ln + t0 + tb, acc[j]);
}

} // anonymous namespace

// ---------------------------------------------------------------------------
extern "C" void kernel_launch(void* const* d_in, const int* in_sizes, int n_in,
                              void* d_out, int out_size)
{
    (void)in_sizes; (void)n_in; (void)out_size;
    const float* x          = (const float*)d_in[0];
    const float* mels       = (const float*)d_in[1];
    const float* input_w    = (const float*)d_in[2];
    const float* input_b    = (const float*)d_in[3];
    const float* mel_w      = (const float*)d_in[4];
    const float* mel_b      = (const float*)d_in[5];
    const float* blk_dil_w  = (const float*)d_in[6];
    const float* blk_dil_b  = (const float*)d_in[7];
    const float* blk_cond_w = (const float*)d_in[8];
    const float* blk_cond_b = (const float*)d_in[9];
    const float* blk_skip_w = (const float*)d_in[10];
    const float* blk_skip_b = (const float*)d_in[11];
    const float* blk_res_w  = (const float*)d_in[12];
    const float* blk_res_b  = (const float*)d_in[13];
    const float* post1_w    = (const float*)d_in[14];
    const float* post1_b    = (const float*)d_in[15];
    const float* post2_w    = (const float*)d_in[16];
    const float* post2_b    = (const float*)d_in[17];

    cudaFuncSetAttribute(z_kernel,  cudaFuncAttributeMaxDynamicSharedMemorySize, Z_SMF  * 4);
    cudaFuncSetAttribute(sr_kernel, cudaFuncAttributeMaxDynamicSharedMemorySize, SR_SMF * 4);
    cudaFuncSetAttribute(p1_kernel, cudaFuncAttributeMaxDynamicSharedMemorySize, P1_SMF * 4);
    cudaFuncSetAttribute(p2_kernel, cudaFuncAttributeMaxDynamicSharedMemorySize, P2_SMF * 4);

    cond_kernel<<<dim3(Ln / 128, Bn), 256>>>(mels, mel_w, mel_b);
    init_kernel<<<512, 256>>>(x, input_w, input_b);

    for (int i = 0; i < NBn; i++) {
        z_kernel<<<dim3(Ln / 128, Bn), 256, Z_SMF * 4>>>(
            blk_dil_w, blk_dil_b, blk_cond_w, blk_cond_b, i);
        sr_kernel<<<dim3(Ln / 128, Bn), 256, SR_SMF * 4>>>(
            blk_skip_w, blk_skip_b, blk_res_w, blk_res_b, i);
    }

    p1_kernel<<<dim3(Ln / 64, Bn), 256, P1_SMF * 4>>>(post1_w, post1_b);
    p2_kernel<<<dim3(Ln / 64, Bn, 2), 256, P2_SMF * 4>>>(post2_w, post2_b, (float*)d_out);
}

// round 2
// speedup vs baseline: 1.8341x; 1.8341x over previous
#include <cuda_runtime.h>

// ---------------------------------------------------------------------------
// WaveNet Mel2Raw — tf32 mma.sync fused-block implementation
// B=2, L=32512, R=64, S=128, NM=80, NC=256, NB=30, KC=2, HOP=256, UK=512
// Per block: one fused kernel (z-GEMM K=208 -> gate -> skip/res GEMMs K=64),
// res double-buffered to avoid cross-CTA halo races.
// ---------------------------------------------------------------------------

namespace {

constexpr int Bn  = 2;
constexpr int Ln  = 32512;
constexpr int Rn  = 64;
constexpr int Sn  = 128;
constexpr int NMn = 80;
constexpr int NCn = 256;
constexpr int NBn = 30;

constexpr int AP = 136;   // fused-kernel smem pitch (136 mod 32 == 8 -> conflict-free B loads)
constexpr int PP = 72;    // post-kernel smem pitch  (72  mod 32 == 8)

// Scratch (static device globals: allocation-free, graph-safe)
__device__ float g_cond[Bn * NMn * Ln];
__device__ float g_resA[Bn * Rn  * Ln];
__device__ float g_resB[Bn * Rn  * Ln];
__device__ float g_skip[Bn * Sn  * Ln];
__device__ float g_y1  [Bn * NCn * Ln];

__device__ __forceinline__ float ex2f(float x) {
    float y; asm("ex2.approx.f32 %0, %1;" : "=f"(y) : "f"(x)); return y;
}
__device__ __forceinline__ float rcpf(float x) {
    float y; asm("rcp.approx.f32 %0, %1;" : "=f"(y) : "f"(x)); return y;
}
// tanh(f) * sigmoid(g) via EX2/RCP
__device__ __forceinline__ float gate_fn(float f, float g) {
    float ef = ex2f(2.8853900817779268f * f);               // e^(2f)
    float th = 1.0f - 2.0f * rcpf(ef + 1.0f);               // tanh(f)
    float sg = rcpf(1.0f + ex2f(-1.4426950408889634f * g)); // sigmoid(g)
    return th * sg;
}
__device__ __forceinline__ unsigned f2tf(float x) {
    unsigned u; asm("cvt.rna.tf32.f32 %0, %1;" : "=r"(u) : "f"(x)); return u;
}

// mma.sync m16n8k8 tf32, fp32 accumulate (in place)
__device__ __forceinline__ void mma8(float c[4], const unsigned a[4], const unsigned b[2]) {
    asm volatile(
        "mma.sync.aligned.m16n8k8.row.col.f32.tf32.tf32.f32 "
        "{%0,%1,%2,%3},{%4,%5,%6,%7},{%8,%9},{%0,%1,%2,%3};"
        : "+f"(c[0]), "+f"(c[1]), "+f"(c[2]), "+f"(c[3])
        : "r"(a[0]), "r"(a[1]), "r"(a[2]), "r"(a[3]), "r"(b[0]), "r"(b[1]));
}

// Warp tile 32(M) x 64(N), K = nk*8. A from global row-major: A[r*as + k*am + ao].
// B (tf32 bits) from smem: sB[(rowbase+k)*pitch + n].
__device__ __forceinline__ void gemm_seg2(
    float acc[2][8][4], const unsigned* __restrict__ sB, int pitch,
    int rowbase, int nk, const float* __restrict__ A, int as, int am, int ao,
    int m0, int n0, int gid, int tig)
{
    #pragma unroll 2
    for (int ks = 0; ks < nk; ks++) {
        unsigned a[2][4];
        const int k = ks * 8 + tig;
        #pragma unroll
        for (int mi = 0; mi < 2; mi++) {
            const float* Ar0 = A + (m0 + mi * 16 + gid) * as;
            const float* Ar1 = Ar0 + 8 * as;
            a[mi][0] = f2tf(Ar0[k * am + ao]);
            a[mi][1] = f2tf(Ar1[k * am + ao]);
            a[mi][2] = f2tf(Ar0[(k + 4) * am + ao]);
            a[mi][3] = f2tf(Ar1[(k + 4) * am + ao]);
        }
        const unsigned* b0 = sB + (rowbase + ks * 8 + tig) * pitch + n0 + gid;
        const unsigned* b1 = b0 + 4 * pitch;
        #pragma unroll
        for (int j = 0; j < 8; j++) {
            unsigned bf[2] = { b0[j * 8], b1[j * 8] };
            mma8(acc[0][j], a[0], bf);
            mma8(acc[1][j], a[1], bf);
        }
    }
}

// Warp tile 16(M) x 64(N) variant (res GEMM).
__device__ __forceinline__ void gemm_seg1(
    float acc[8][4], const unsigned* __restrict__ sB, int pitch, int nk,
    const float* __restrict__ A, int as, int m0, int n0, int gid, int tig)
{
    #pragma unroll 2
    for (int ks = 0; ks < nk; ks++) {
        unsigned a[4];
        const int k = ks * 8 + tig;
        const float* Ar0 = A + (m0 + gid) * as;
        const float* Ar1 = Ar0 + 8 * as;
        a[0] = f2tf(Ar0[k]);     a[1] = f2tf(Ar1[k]);
        a[2] = f2tf(Ar0[k + 4]); a[3] = f2tf(Ar1[k + 4]);
        const unsigned* b0 = sB + (ks * 8 + tig) * pitch + n0 + gid;
        const unsigned* b1 = b0 + 4 * pitch;
        #pragma unroll
        for (int j = 0; j < 8; j++) {
            unsigned bf[2] = { b0[j * 8], b1[j * 8] };
            mma8(acc[j], a, bf);
        }
    }
}

// ---------------------------------------------------------------------------
// cond: transposed conv -> exactly 2 taps (q = t>>8 always in-bounds)
// ---------------------------------------------------------------------------
__global__ __launch_bounds__(256) void cond_kernel(
    const float* __restrict__ mels, const float* __restrict__ mel_w,
    const float* __restrict__ mel_b)
{
    __shared__ float m0s[NMn], m1s[NMn];
    const int b  = blockIdx.y;
    const int t0 = blockIdx.x * 128;
    const int q  = t0 >> 8;
    const int tid = threadIdx.x;
    if (tid < NMn) {
        m0s[tid] = mels[(b * NMn + tid) * 128 + q];
        m1s[tid] = mels[(b * NMn + tid) * 128 + q + 1];
    }
    __syncthreads();
    for (int j = tid; j < NMn * 128; j += 256) {
        const int c  = j >> 7;
        const int tt = j & 127;
        const int t  = t0 + tt;
        const int r  = t & 255;
        const float* w = mel_w + c * (NMn * 512);
        float acc = mel_b[c];
        #pragma unroll 4
        for (int ci = 0; ci < NMn; ci++) {
            acc += w[ci * 512 + 255 - r] * m0s[ci];
            acc += w[ci * 512 + 511 - r] * m1s[ci];
        }
        g_cond[(b * NMn + c) * Ln + t] = acc;
    }
}

// ---------------------------------------------------------------------------
// init: resA = input_w[r]*x + input_b[r];  skip = 0
// ---------------------------------------------------------------------------
__global__ void init_kernel(const float* __restrict__ x,
                            const float* __restrict__ iw,
                            const float* __restrict__ ib)
{
    const int stride = gridDim.x * blockDim.x;
    const int tid0   = blockIdx.x * blockDim.x + threadIdx.x;
    for (int i = tid0; i < Bn * Rn * Ln; i += stride) {
        const int t = i % Ln;
        const int r = (i / Ln) % Rn;
        const int b = i / (Ln * Rn);
        g_resA[i] = iw[r] * x[b * Ln + t] + ib[r];
    }
    for (int i = tid0; i < Bn * Sn * Ln; i += stride) g_skip[i] = 0.0f;
}

// ---------------------------------------------------------------------------
// Fused block kernel: z (K=208 tf32 GEMM) -> gate -> skip+= / res_out = res_in + ...
// CTA: 256 threads (8 warps, 4 M-groups x 2 N-groups), tile = 128 co x 128 t
// ---------------------------------------------------------------------------
constexpr int BLK_SMEM = 208 * AP * 4;   // 113152 B

__global__ __launch_bounds__(256, 2) void block_kernel(
    const float* __restrict__ dil_w,  const float* __restrict__ dil_b,
    const float* __restrict__ cond_w, const float* __restrict__ cond_b,
    const float* __restrict__ skip_w, const float* __restrict__ skip_b,
    const float* __restrict__ res_w,  const float* __restrict__ res_b,
    const float* __restrict__ res_in, float* __restrict__ res_out,
    int blk)
{
    extern __shared__ unsigned smu[];
    unsigned* s_act = smu;                 // [208][AP] tf32 bits (rows: 0-63 prev, 64-127 cur, 128-207 cond)
    float*    s_z   = (float*)smu;         // alias [128][AP]  (valid after GEMM1)
    unsigned* s_h   = smu + 128 * AP;      // [64][AP] tf32 bits

    const int d = 1 << (blk % 10);
    const float* wd  = dil_w  + blk * (128 * 64 * 2);
    const float* wc  = cond_w + blk * (128 * NMn);
    const float* wsk = skip_w + blk * (Sn * Rn);
    const float* wre = res_w  + blk * (Rn * Rn);
    const float* bd  = dil_b  + blk * 128;
    const float* bc  = cond_b + blk * 128;
    const float* bs  = skip_b + blk * Sn;
    const float* br  = res_b  + blk * Rn;

    const int b   = blockIdx.y;
    const int t0  = blockIdx.x * 128;
    const int tid = threadIdx.x;

    // ---- stage activations (fp32 -> tf32 bits) ----
    const float* resb = res_in + b * (Rn * Ln);
    for (int i = tid; i < 64 * 128; i += 256) {
        const int ci = i >> 7, tt = i & 127;
        s_act[(64 + ci) * AP + tt] = f2tf(resb[ci * Ln + t0 + tt]);
        const int tp = t0 + tt - d;
        const float pv = (tp >= 0) ? resb[ci * Ln + tp] : 0.0f;
        s_act[ci * AP + tt] = f2tf(pv);
    }
    const float* condb = g_cond + b * (NMn * Ln);
    for (int i = tid; i < NMn * 128; i += 256) {
        const int ci = i >> 7, tt = i & 127;
        s_act[(128 + ci) * AP + tt] = f2tf(condb[ci * Ln + t0 + tt]);
    }
    __syncthreads();

    const int lane = tid & 31, warp = tid >> 5;
    const int gid = lane >> 2, tig = lane & 3;
    const int m0 = (warp & 3) * 32, n0 = (warp >> 2) * 64;

    // ---- GEMM1: z[128, 128t], K = 64(prev) + 64(cur) + 80(cond) ----
    float acc[2][8][4];
    #pragma unroll
    for (int mi = 0; mi < 2; mi++) {
        const int r0 = m0 + mi * 16 + gid;
        const float z0 = bd[r0] + bc[r0];
        const float z1 = bd[r0 + 8] + bc[r0 + 8];
        #pragma unroll
        for (int j = 0; j < 8; j++) {
            acc[mi][j][0] = z0; acc[mi][j][1] = z0;
            acc[mi][j][2] = z1; acc[mi][j][3] = z1;
        }
    }
    gemm_seg2(acc, s_act, AP,   0,  8, wd, 128, 2, 0, m0, n0, gid, tig);  // tap0 * prev
    gemm_seg2(acc, s_act, AP,  64,  8, wd, 128, 2, 1, m0, n0, gid, tig);  // tap1 * cur
    gemm_seg2(acc, s_act, AP, 128, 10, wc,  80, 1, 0, m0, n0, gid, tig);  // cond

    __syncthreads();   // all warps done reading s_act before aliasing as s_z
    #pragma unroll
    for (int mi = 0; mi < 2; mi++) {
        const int r0 = m0 + mi * 16 + gid;
        #pragma unroll
        for (int j = 0; j < 8; j++) {
            const int c = n0 + j * 8 + tig * 2;
            s_z[r0 * AP + c]           = acc[mi][j][0];
            s_z[r0 * AP + c + 1]       = acc[mi][j][1];
            s_z[(r0 + 8) * AP + c]     = acc[mi][j][2];
            s_z[(r0 + 8) * AP + c + 1] = acc[mi][j][3];
        }
    }
    __syncthreads();

    // ---- gate: h = tanh(z_f) * sigmoid(z_g) -> tf32 ----
    for (int i = tid; i < 64 * 128; i += 256) {
        const int c = i >> 7, tt = i & 127;
        s_h[c * AP + tt] = f2tf(gate_fn(s_z[c * AP + tt], s_z[(c + 64) * AP + tt]));
    }
    __syncthreads();

    // ---- GEMM2: skip += Ws*h + bs  (M=128, K=64) ----
    #pragma unroll
    for (int mi = 0; mi < 2; mi++) {
        const int r0 = m0 + mi * 16 + gid;
        const float z0 = bs[r0], z1 = bs[r0 + 8];
        #pragma unroll
        for (int j = 0; j < 8; j++) {
            acc[mi][j][0] = z0; acc[mi][j][1] = z0;
            acc[mi][j][2] = z1; acc[mi][j][3] = z1;
        }
    }
    gemm_seg2(acc, s_h, AP, 0, 8, wsk, 64, 1, 0, m0, n0, gid, tig);

    float* skb = g_skip + b * (Sn * Ln);
    #pragma unroll
    for (int mi = 0; mi < 2; mi++) {
        const int r0 = m0 + mi * 16 + gid;
        #pragma unroll
        for (int j = 0; j < 8; j++) {
            const int c = t0 + n0 + j * 8 + tig * 2;
            float* p = skb + r0 * Ln + c;
            p[0] += acc[mi][j][0]; p[1] += acc[mi][j][1];
            float* q = skb + (r0 + 8) * Ln + c;
            q[0] += acc[mi][j][2]; q[1] += acc[mi][j][3];
        }
    }

    // ---- GEMM3: res_out = res_in + Wr*h + br  (M=64, K=64) ----
    float accr[8][4];
    const int mr = (warp & 3) * 16;
    {
        const int r0 = mr + gid;
        const float z0 = br[r0], z1 = br[r0 + 8];
        #pragma unroll
        for (int j = 0; j < 8; j++) {
            accr[j][0] = z0; accr[j][1] = z0;
            accr[j][2] = z1; accr[j][3] = z1;
        }
    }
    gemm_seg1(accr, s_h, AP, 8, wre, 64, mr, n0, gid, tig);

    float* rob = res_out + b * (Rn * Ln);
    {
        const int r0 = mr + gid;
        #pragma unroll
        for (int j = 0; j < 8; j++) {
            const int c = t0 + n0 + j * 8 + tig * 2;
            const float* pi = resb + r0 * Ln + c;
            float* po = rob + r0 * Ln + c;
            po[0] = pi[0] + accr[j][0];
            po[1] = pi[1] + accr[j][1];
            const float* qi = resb + (r0 + 8) * Ln + c;
            float* qo = rob + (r0 + 8) * Ln + c;
            qo[0] = qi[0] + accr[j][2];
            qo[1] = qi[1] + accr[j][3];
        }
    }
}

// ---------------------------------------------------------------------------
// post1: y1 = W1 * relu(skip) + b1   (M=256, K=128, 64-t tiles)
// ---------------------------------------------------------------------------
constexpr int P1_SMEM = 128 * PP * 4;    // 36864 B

__global__ __launch_bounds__(256, 2) void p1_kernel(
    const float* __restrict__ w1, const float* __restrict__ b1)
{
    extern __shared__ unsigned smu[];
    unsigned* s_a = smu;                 // [128][PP]
    const int b = blockIdx.y, t0 = blockIdx.x * 64, tid = threadIdx.x;

    const float* skb = g_skip + b * (Sn * Ln);
    for (int i = tid; i < 128 * 64; i += 256) {
        const int ci = i >> 6, tt = i & 63;
        s_a[ci * PP + tt] = f2tf(fmaxf(skb[ci * Ln + t0 + tt], 0.0f));
    }
    __syncthreads();

    const int lane = tid & 31, warp = tid >> 5;
    const int gid = lane >> 2, tig = lane & 3;
    const int m0 = warp * 32;

    float acc[2][8][4];
    #pragma unroll
    for (int mi = 0; mi < 2; mi++) {
        const int r0 = m0 + mi * 16 + gid;
        const float z0 = b1[r0], z1 = b1[r0 + 8];
        #pragma unroll
        for (int j = 0; j < 8; j++) {
            acc[mi][j][0] = z0; acc[mi][j][1] = z0;
            acc[mi][j][2] = z1; acc[mi][j][3] = z1;
        }
    }
    gemm_seg2(acc, s_a, PP, 0, 16, w1, 128, 1, 0, m0, 0, gid, tig);

    float* yb = g_y1 + b * (NCn * Ln);
    #pragma unroll
    for (int mi = 0; mi < 2; mi++) {
        const int r0 = m0 + mi * 16 + gid;
        #pragma unroll
        for (int j = 0; j < 8; j++) {
            const int c = t0 + j * 8 + tig * 2;
            float* p = yb + r0 * Ln + c;
            p[0] = acc[mi][j][0]; p[1] = acc[mi][j][1];
            float* q = yb + (r0 + 8) * Ln + c;
            q[0] = acc[mi][j][2]; q[1] = acc[mi][j][3];
        }
    }
}

// ---------------------------------------------------------------------------
// post2: out = W2 * relu(y1) + b2   (M=256, K=256, 64-t tiles)
// ---------------------------------------------------------------------------
constexpr int P2_SMEM = 256 * PP * 4;    // 73728 B

__global__ __launch_bounds__(256, 2) void p2_kernel(
    const float* __restrict__ w2, const float* __restrict__ b2,
    float* __restrict__ out)
{
    extern __shared__ unsigned smu[];
    unsigned* s_a = smu;                 // [256][PP]
    const int b = blockIdx.y, t0 = blockIdx.x * 64, tid = threadIdx.x;

    const float* yb = g_y1 + b * (NCn * Ln);
    for (int i = tid; i < 256 * 64; i += 256) {
        const int ci = i >> 6, tt = i & 63;
        s_a[ci * PP + tt] = f2tf(fmaxf(yb[ci * Ln + t0 + tt], 0.0f));
    }
    __syncthreads();

    const int lane = tid & 31, warp = tid >> 5;
    const int gid = lane >> 2, tig = lane & 3;
    const int m0 = warp * 32;

    float acc[2][8][4];
    #pragma unroll
    for (int mi = 0; mi < 2; mi++) {
        const int r0 = m0 + mi * 16 + gid;
        const float z0 = b2[r0], z1 = b2[r0 + 8];
        #pragma unroll
        for (int j = 0; j < 8; j++) {
            acc[mi][j][0] = z0; acc[mi][j][1] = z0;
            acc[mi][j][2] = z1; acc[mi][j][3] = z1;
        }
    }
    gemm_seg2(acc, s_a, PP, 0, 32, w2, 256, 1, 0, m0, 0, gid, tig);

    float* ob = out + b * (NCn * Ln);
    #pragma unroll
    for (int mi = 0; mi < 2; mi++) {
        const int r0 = m0 + mi * 16 + gid;
        #pragma unroll
        for (int j = 0; j < 8; j++) {
            const int c = t0 + j * 8 + tig * 2;
            float* p = ob + r0 * Ln + c;
            p[0] = acc[mi][j][0]; p[1] = acc[mi][j][1];
            float* q = ob + (r0 + 8) * Ln + c;
            q[0] = acc[mi][j][2]; q[1] = acc[mi][j][3];
        }
    }
}

} // anonymous namespace

// ---------------------------------------------------------------------------
extern "C" void kernel_launch(void* const* d_in, const int* in_sizes, int n_in,
                              void* d_out, int out_size)
{
    (void)in_sizes; (void)n_in; (void)out_size;
    const float* x          = (const float*)d_in[0];
    const float* mels       = (const float*)d_in[1];
    const float* input_w    = (const float*)d_in[2];
    const float* input_b    = (const float*)d_in[3];
    const float* mel_w      = (const float*)d_in[4];
    const float* mel_b      = (const float*)d_in[5];
    const float* blk_dil_w  = (const float*)d_in[6];
    const float* blk_dil_b  = (const float*)d_in[7];
    const float* blk_cond_w = (const float*)d_in[8];
    const float* blk_cond_b = (const float*)d_in[9];
    const float* blk_skip_w = (const float*)d_in[10];
    const float* blk_skip_b = (const float*)d_in[11];
    const float* blk_res_w  = (const float*)d_in[12];
    const float* blk_res_b  = (const float*)d_in[13];
    const float* post1_w    = (const float*)d_in[14];
    const float* post1_b    = (const float*)d_in[15];
    const float* post2_w    = (const float*)d_in[16];
    const float* post2_b    = (const float*)d_in[17];

    cudaFuncSetAttribute(block_kernel, cudaFuncAttributeMaxDynamicSharedMemorySize, BLK_SMEM);
    cudaFuncSetAttribute(p1_kernel,    cudaFuncAttributeMaxDynamicSharedMemorySize, P1_SMEM);
    cudaFuncSetAttribute(p2_kernel,    cudaFuncAttributeMaxDynamicSharedMemorySize, P2_SMEM);

    float* resA; cudaGetSymbolAddress((void**)&resA, g_resA);
    float* resB; cudaGetSymbolAddress((void**)&resB, g_resB);

    cond_kernel<<<dim3(Ln / 128, Bn), 256>>>(mels, mel_w, mel_b);
    init_kernel<<<512, 256>>>(x, input_w, input_b);

    for (int i = 0; i < NBn; i++) {
        const float* rin = (i & 1) ? resB : resA;
        float*       rout = (i & 1) ? resA : resB;
        block_kernel<<<dim3(Ln / 128, Bn), 256, BLK_SMEM>>>(
            blk_dil_w, blk_dil_b, blk_cond_w, blk_cond_b,
            blk_skip_w, blk_skip_b, blk_res_w, blk_res_b,
            rin, rout, i);
    }

    p1_kernel<<<dim3(Ln / 64, Bn), 256, P1_SMEM>>>(post1_w, post1_b);
    p2_kernel<<<dim3(Ln / 64, Bn), 256, P2_SMEM>>>(post2_w, post2_b, (float*)d_out);
}